// round 12
// baseline (speedup 1.0000x reference)
#include <cuda_runtime.h>
#include <cuda_fp16.h>
#include <cstdint>

#define SS 8
#define NN 2048
#define KK 64
#define NPAIR (SS * NN / 2)
#define PI_F 3.14159265358979323846f

// ---------------- precomputed tables (written by precompute_kernel) ----------
__device__ float g_td[4][31];      // td table per type-pair
__device__ float g_base[4][64];    // td @ gw0[:31] + gb0
__device__ float g_v[64];          // gw0[31,:]
// W^T fragments (fp16) in mma.sync B layout: [nt(16)][ks(4)][lane(32)]
__device__ uint2 g_bfrag[2048];

// ---------------- helpers ----------------------------------------------------
__device__ __forceinline__ uint32_t smem_u32(const void* p) {
    uint32_t a;
    asm("{ .reg .u64 t; cvta.to.shared.u64 t, %1; cvt.u32.u64 %0, t; }" : "=r"(a) : "l"(p));
    return a;
}
__device__ __forceinline__ void ldm4(uint32_t* r, uint32_t addr) {
    asm volatile("ldmatrix.sync.aligned.m8n8.x4.shared.b16 {%0,%1,%2,%3}, [%4];"
                 : "=r"(r[0]), "=r"(r[1]), "=r"(r[2]), "=r"(r[3]) : "r"(addr));
}
__device__ __forceinline__ void mma16816(float* c, const uint32_t* a, uint2 b) {
    asm volatile("mma.sync.aligned.m16n8k16.row.col.f32.f16.f16.f32 "
                 "{%0,%1,%2,%3}, {%4,%5,%6,%7}, {%8,%9}, {%0,%1,%2,%3};"
                 : "+f"(c[0]), "+f"(c[1]), "+f"(c[2]), "+f"(c[3])
                 : "r"(a[0]), "r"(a[1]), "r"(a[2]), "r"(a[3]), "r"(b.x), "r"(b.y));
}
__device__ __forceinline__ uint32_t pack_h2(float lo, float hi) {
    __half l = __float2half_rn(lo);
    __half h = __float2half_rn(hi);
    return (uint32_t)__half_as_ushort(l) | ((uint32_t)__half_as_ushort(h) << 16);
}
// packed f32x2
typedef unsigned long long ull;
__device__ __forceinline__ ull pk2f(float lo, float hi) {
    ull r; asm("mov.b64 %0, {%1, %2};" : "=l"(r) : "f"(lo), "f"(hi)); return r;
}
__device__ __forceinline__ ull fma2(ull a, ull b, ull c) {
    ull d; asm("fma.rn.f32x2 %0, %1, %2, %3;" : "=l"(d) : "l"(a), "l"(b), "l"(c)); return d;
}
__device__ __forceinline__ float2 upk2(ull v) {
    float2 r; asm("mov.b64 {%0, %1}, %2;" : "=f"(r.x), "=f"(r.y) : "l"(v)); return r;
}

// ---------------- parallel precompute (512 threads) --------------------------
__global__ void precompute_kernel(const float* __restrict__ ew0, const float* __restrict__ eb0,
                                  const float* __restrict__ ew1, const float* __restrict__ eb1,
                                  const float* __restrict__ fw0, const float* __restrict__ fb0,
                                  const float* __restrict__ fw1, const float* __restrict__ fb1,
                                  const float* __restrict__ gw0, const float* __restrict__ gb0,
                                  const float* __restrict__ gw1) {
    __shared__ float sh16[2][4][16];
    __shared__ float sh32[4][32];
    __shared__ float shf[4][32];
    __shared__ float shtd[4][31];
    const int t = threadIdx.x;

    if (t < 128) {
        int rev = t >> 6, p = (t >> 4) & 3, i = t & 15;
        float a = (float)(p >> 1), b = (float)(p & 1);
        float x0 = rev ? b : a, x1 = rev ? a : b;
        sh16[rev][p][i] = fmaxf(x0 * ew0[i] + x1 * ew0[16 + i] + eb0[i], 0.f);
    }
    __syncthreads();
    if (t < 128) {
        int p = t >> 5, o = t & 31;
        float s0 = eb1[o], s1 = eb1[o];
        for (int i = 0; i < 16; ++i) {
            s0 += sh16[0][p][i] * ew1[i * 32 + o];
            s1 += sh16[1][p][i] * ew1[i * 32 + o];
        }
        sh32[p][o] = fmaxf(s0, 0.f) + fmaxf(s1, 0.f);
    }
    __syncthreads();
    if (t < 128) {
        int p = t >> 5, o = t & 31;
        float acc = fb0[o];
        for (int i = 0; i < 32; ++i) acc += sh32[p][i] * fw0[i * 32 + o];
        shf[p][o] = fmaxf(acc, 0.f);
    }
    __syncthreads();
    if (t < 124) {
        int p = t / 31, o = t % 31;
        float acc = fb1[o];
        for (int i = 0; i < 32; ++i) acc += shf[p][i] * fw1[i * 31 + o];
        float td = fmaxf(acc, 0.f);
        g_td[p][o] = td;
        shtd[p][o] = td;
    }
    __syncthreads();
    if (t < 256) {
        int p = t >> 6, j = t & 63;
        float acc = gb0[j];
        for (int i = 0; i < 31; ++i) acc += shtd[p][i] * gw0[i * 64 + j];
        g_base[p][j] = acc;
    }
    if (t < 64) g_v[t] = gw0[31 * 64 + t];

    // B fragments: fp16; mma.sync m16n8k16 col-major B layout
    for (int idx = t; idx < 2048; idx += 512) {
        int lane = idx & 31;
        int ks   = (idx >> 5) & 3;
        int nt   = idx >> 7;
        int e    = nt * 8 + (lane >> 2);
        int j0   = ks * 16 + (lane & 3) * 2;
        g_bfrag[idx] = make_uint2(
            pack_h2(gw1[j0 * 128 + e],       gw1[(j0 + 1) * 128 + e]),
            pack_h2(gw1[(j0 + 8) * 128 + e], gw1[(j0 + 9) * 128 + e]));
    }
}

// ---------------- fused main kernel: one CTA per 2 (s,n) pairs ---------------
__global__ __launch_bounds__(128, 4)
void desc_kernel(const float* __restrict__ inputs,
                 const int*   __restrict__ types,
                 const int*   __restrict__ neigh,
                 const float* __restrict__ length,
                 const float* __restrict__ gb1,
                 float*       __restrict__ out)
{
    // single Y panel: 128 rows x 64 fp16 (128B rows), 16B-chunk XOR swizzle
    __shared__ __align__(128) unsigned char ypan[128 * 128];
    __shared__ __align__(16) float4 rts4[128];
    __shared__ __align__(16) float base_s[4 * 68];
    __shared__ __align__(16) float v_s[64];
    __shared__ __align__(16) float td_s[4 * 34];
    __shared__ __align__(16) float4 T_part[2][128];  // [kh][snh*64 + j]
    __shared__ __align__(16) float4 A_s[2][128];     // lower-half partial (+T)
    __shared__ __align__(16) float4 A2_s[2][128];    // upper-half partial

    const int t    = threadIdx.x;
    const int w    = t >> 5;
    const int lane = t & 31;

    // ---- B fragment preload ----
    uint2 bfr[4][4];
#pragma unroll
    for (int ntl = 0; ntl < 4; ++ntl)
#pragma unroll
        for (int ks = 0; ks < 4; ++ks)
            bfr[ntl][ks] = g_bfrag[(((w * 4 + ntl) * 4) + ks) * 32 + lane];

    // ---- stage tables ----
    for (int i = t; i < 256; i += 128) base_s[(i >> 6) * 68 + (i & 63)] = ((const float*)g_base)[i];
    if (t < 64) v_s[t] = g_v[t];
    for (int i = t; i < 124; i += 128) td_s[(i / 31) * 34 + (i % 31)] = ((const float*)g_td)[i];
    if (t < 4) { td_s[t * 34 + 31] = 0.f; td_s[t * 34 + 32] = 0.f; td_s[t * 34 + 33] = 0.f; }

    float b1v[8];
#pragma unroll
    for (int cc = 0; cc < 8; ++cc)
        b1v[cc] = gb1[w * 32 + (cc >> 1) * 8 + (lane & 3) * 2 + (cc & 1)];

    // ---- geometry ----
    const int sn = blockIdx.x * 2 + (t >> 6);
    const int s  = sn >> 11;
    const int n  = sn & (NN - 1);
    float sij; int pp;
    {
        int idx = neigh[(size_t)sn * KK + (t & 63)];
        bool msk = idx < 0;
        int i0 = msk ? 0 : idx;
        float Lx = length[0], Ly = length[1], Lz = length[2];
        const float* pc = inputs + ((size_t)s * NN + n) * 3;
        const float* pn = inputs + ((size_t)s * NN + i0) * 3;
        float dx = pn[0] - pc[0];
        float dy = pn[1] - pc[1];
        float dz = pn[2] - pc[2];
        dx -= Lx * rintf(dx / Lx);
        dy -= Ly * rintf(dy / Ly);
        dz -= Lz * rintf(dz / Lz);
        float rsq = dx * dx + dy * dy + dz * dz;
        float rs  = rsq > 0.f ? rsq : 1.0f;
        float inv = rsqrtf(rs);
        float r   = rs * inv;
        float sw;
        if (r < 6.0f)       sw = inv;
        else if (r < 12.0f) { float u = (r - 6.0f) * (1.0f / 6.0f);
                              sw = inv * (0.5f * __cosf(PI_F * u) + 0.5f); }
        else                sw = 0.f;
        bool valid = (!msk) && (rsq > 0.f);
        sij = valid ? sw : 0.f;
        float f = sij * inv;
        rts4[t] = make_float4(sij, dx * f, dy * f, dz * f);
        int ct = types[(size_t)s * NN + n];
        int nt = types[(size_t)s * NN + i0];
        pp = ct * 2 + nt;
    }
    __syncthreads();

    // ---- phase 2: y row t -> fp16, swizzled 16B-chunk stores ----
    {
        const int rx = t & 7;
        const float2* base2 = (const float2*)(base_s + pp * 68);
        const float2* v2    = (const float2*)v_s;
        const float2* td2   = (const float2*)(td_s + pp * 34);
#pragma unroll
        for (int c = 0; c < 8; ++c) {
            uint32_t wh[4];
#pragma unroll
            for (int q = 0; q < 4; ++q) {
                int jp = c * 4 + q;
                float2 b  = base2[jp];
                float2 vv = v2[jp];
                float2 td = td2[jp & 15];
                float y0 = fmaxf(fmaf(sij, vv.x, b.x), 0.f) + td.x;
                float y1 = fmaxf(fmaf(sij, vv.y, b.y), 0.f) + (((jp & 15) < 15) ? td.y : sij);
                wh[q] = pack_h2(y0, y1);
            }
            int off = t * 128 + (c ^ rx) * 16;
            *(uint4*)(ypan + off) = make_uint4(wh[0], wh[1], wh[2], wh[3]);
        }
    }
    __syncthreads();

    // ---- tail partials: T_part[kh][snh*64+j] = sum_{k in half} y[k,j]*rt[k,:] ----
    {
        const int snh = t >> 6;
        const int kh  = (t >> 5) & 1;
        const int jp  = lane;
        const int chunk = jp >> 2, pos = jp & 3;
        const uint32_t* y32 = (const uint32_t*)ypan;
        const int rbase = snh * 64 + kh * 32;
        ull Tj0a = 0ull, Tj0b = 0ull, Tj1a = 0ull, Tj1b = 0ull;
#pragma unroll
        for (int i = 0; i < 32; ++i) {
            const int row = rbase + i;
            uint32_t o = (uint32_t)(row * 32 + ((chunk ^ (row & 7)) << 2) + pos);
            uint32_t yv = y32[o];
            float2 yf = __half22float2(*(const __half2*)&yv);
            ull y0p = pk2f(yf.x, yf.x);
            ull y1p = pk2f(yf.y, yf.y);
            double2 q = *(const double2*)(rts4 + row);
            ull qxy = __double_as_longlong(q.x), qzw = __double_as_longlong(q.y);
            Tj0a = fma2(y0p, qxy, Tj0a);
            Tj0b = fma2(y0p, qzw, Tj0b);
            Tj1a = fma2(y1p, qxy, Tj1a);
            Tj1b = fma2(y1p, qzw, Tj1b);
        }
        float2 a0 = upk2(Tj0a), b0 = upk2(Tj0b);
        float2 a1 = upk2(Tj1a), b1 = upk2(Tj1b);
        T_part[kh][snh * 64 + 2 * jp]     = make_float4(a0.x, a0.y, b0.x, b0.y);
        T_part[kh][snh * 64 + 2 * jp + 1] = make_float4(a1.x, a1.y, b1.x, b1.y);
    }
    __syncthreads();

    const uint32_t y_b = smem_u32(ypan);

    // ---- MMA + fused epilogue: G = Yh * Wh ----
#pragma unroll
    for (int h = 0; h < 2; ++h) {
        ull part01[8], part23[8];
#pragma unroll
        for (int cc = 0; cc < 8; ++cc) { part01[cc] = 0ull; part23[cc] = 0ull; }

#pragma unroll
        for (int mtl = 0; mtl < 4; ++mtl) {
            const int mt = h * 4 + mtl;
            float acc[4][4];
#pragma unroll
            for (int ntl = 0; ntl < 4; ++ntl) {   // bias pre-folded
                acc[ntl][0] = b1v[ntl * 2];
                acc[ntl][1] = b1v[ntl * 2 + 1];
                acc[ntl][2] = b1v[ntl * 2];
                acc[ntl][3] = b1v[ntl * 2 + 1];
            }

            const int arow  = mt * 16 + (lane & 15);
            const int arx   = arow & 7;
            const uint32_t abase = (uint32_t)(arow * 128);
#pragma unroll
            for (int ks = 0; ks < 4; ++ks) {
                uint32_t ah[4];
                uint32_t chsel = (uint32_t)(((ks * 2 + (lane >> 4)) ^ arx) * 16);
                ldm4(ah, y_b + abase + chsel);
#pragma unroll
                for (int ntl = 0; ntl < 4; ++ntl) mma16816(acc[ntl], ah, bfr[ntl][ks]);
            }
            // epilogue: relu + packed A-accumulation
            const int r0 = mt * 16 + (lane >> 2);
            double2 qa = *(const double2*)(rts4 + r0);
            double2 qb = *(const double2*)(rts4 + r0 + 8);
            const ull q0xy = __double_as_longlong(qa.x), q0zw = __double_as_longlong(qa.y);
            const ull q1xy = __double_as_longlong(qb.x), q1zw = __double_as_longlong(qb.y);
#pragma unroll
            for (int cc = 0; cc < 8; ++cc) {
                const int ntl = cc >> 1, c = cc & 1;
                float g0 = fmaxf(acc[ntl][c],     0.f);
                float g1 = fmaxf(acc[ntl][2 + c], 0.f);
                ull g0p = pk2f(g0, g0);
                ull g1p = pk2f(g1, g1);
                part01[cc] = fma2(g0p, q0xy, part01[cc]);
                part23[cc] = fma2(g0p, q0zw, part23[cc]);
                part01[cc] = fma2(g1p, q1xy, part01[cc]);
                part23[cc] = fma2(g1p, q1zw, part23[cc]);
            }
        }

        // 2-round reduce: lanes l and l^16 jointly hold the sum of the 8 groups
#pragma unroll
        for (int cc = 0; cc < 8; ++cc) {
            float2 u01 = upk2(part01[cc]);
            float2 u23 = upk2(part23[cc]);
            float pv[4] = {u01.x, u01.y, u23.x, u23.y};
#pragma unroll
            for (int d = 0; d < 4; ++d) {
                float v = pv[d];
                v += __shfl_xor_sync(0xffffffffu, v, 4);
                v += __shfl_xor_sync(0xffffffffu, v, 8);
                pv[d] = v;
            }
            if ((lane & 15) < 4) {
                int e = w * 32 + (cc >> 1) * 8 + (lane & 3) * 2 + (cc & 1);
                if (lane < 4) {
                    float4 Ta = T_part[0][h * 64 + (e & 63)];
                    float4 Tb = T_part[1][h * 64 + (e & 63)];
                    A_s[h][e] = make_float4(pv[0] + Ta.x + Tb.x, pv[1] + Ta.y + Tb.y,
                                            pv[2] + Ta.z + Tb.z, pv[3] + Ta.w + Tb.w);
                } else {
                    A2_s[h][e] = make_float4(pv[0], pv[1], pv[2], pv[3]);
                }
            }
        }
    }
    __syncthreads();

    // ---- merge the two half-partials: A = A_s + A2_s (2 elements/thread) ----
#pragma unroll
    for (int i = 0; i < 2; ++i) {
        int idx = t + i * 128;
        float4 a = A_s[idx >> 7][idx & 127];
        float4 b = A2_s[idx >> 7][idx & 127];
        A_s[idx >> 7][idx & 127] = make_float4(a.x + b.x, a.y + b.y, a.z + b.z, a.w + b.w);
    }
    __syncthreads();

    // ---- D[e,m] = sum_d A[e,d] * A[m,d] per sn-half ----
    const int e = t;
#pragma unroll
    for (int h = 0; h < 2; ++h) {
        float4 a = A_s[h][e];
        size_t gsn = (size_t)blockIdx.x * 2 + h;
        float4* op = (float4*)(out + (gsn * 128 + e) * 16);
#pragma unroll
        for (int m4 = 0; m4 < 4; ++m4) {
            float4 b0 = A_s[h][4 * m4 + 0];
            float4 b1 = A_s[h][4 * m4 + 1];
            float4 b2 = A_s[h][4 * m4 + 2];
            float4 b3 = A_s[h][4 * m4 + 3];
            float4 o;
            o.x = a.x * b0.x + a.y * b0.y + a.z * b0.z + a.w * b0.w;
            o.y = a.x * b1.x + a.y * b1.y + a.z * b1.z + a.w * b1.w;
            o.z = a.x * b2.x + a.y * b2.y + a.z * b2.z + a.w * b2.w;
            o.w = a.x * b3.x + a.y * b3.y + a.z * b3.z + a.w * b3.w;
            op[m4] = o;
        }
    }
}

// ---------------- launch -----------------------------------------------------
extern "C" void kernel_launch(void* const* d_in, const int* in_sizes, int n_in,
                              void* d_out, int out_size) {
    const float* inputs = (const float*)d_in[0];
    const int*   types  = (const int*)d_in[1];
    const int*   neigh  = (const int*)d_in[2];
    const float* length = (const float*)d_in[3];
    const float* ew0 = (const float*)d_in[4];
    const float* eb0 = (const float*)d_in[5];
    const float* ew1 = (const float*)d_in[6];
    const float* eb1 = (const float*)d_in[7];
    const float* fw0 = (const float*)d_in[8];
    const float* fb0 = (const float*)d_in[9];
    const float* fw1 = (const float*)d_in[10];
    const float* fb1 = (const float*)d_in[11];
    const float* gw0 = (const float*)d_in[12];
    const float* gb0 = (const float*)d_in[13];
    const float* gw1 = (const float*)d_in[14];
    const float* gb1 = (const float*)d_in[15];

    precompute_kernel<<<1, 512>>>(ew0, eb0, ew1, eb1, fw0, fb0, fw1, fb1, gw0, gb0, gw1);
    desc_kernel<<<NPAIR, 128>>>(inputs, types, neigh, length, gb1, (float*)d_out);
}

// round 13
// speedup vs baseline: 1.0909x; 1.0909x over previous
#include <cuda_runtime.h>
#include <cuda_fp16.h>
#include <cstdint>

#define SS 8
#define NN 2048
#define KK 64
#define NPAIR (SS * NN / 2)
#define PI_F 3.14159265358979323846f

// ---------------- precomputed tables (written by precompute_kernel) ----------
__device__ float g_td[4][31];      // td table per type-pair
__device__ float g_base[4][64];    // td @ gw0[:31] + gb0
__device__ float g_v[64];          // gw0[31,:]
// W^T fragments (fp16) in mma.sync B layout: [nt(16)][ks(4)][lane(32)]
__device__ uint2 g_bfrag[2048];

// ---------------- helpers ----------------------------------------------------
__device__ __forceinline__ uint32_t smem_u32(const void* p) {
    uint32_t a;
    asm("{ .reg .u64 t; cvta.to.shared.u64 t, %1; cvt.u32.u64 %0, t; }" : "=r"(a) : "l"(p));
    return a;
}
__device__ __forceinline__ void ldm4(uint32_t* r, uint32_t addr) {
    asm volatile("ldmatrix.sync.aligned.m8n8.x4.shared.b16 {%0,%1,%2,%3}, [%4];"
                 : "=r"(r[0]), "=r"(r[1]), "=r"(r[2]), "=r"(r[3]) : "r"(addr));
}
__device__ __forceinline__ void mma16816(float* c, const uint32_t* a, uint2 b) {
    asm volatile("mma.sync.aligned.m16n8k16.row.col.f32.f16.f16.f32 "
                 "{%0,%1,%2,%3}, {%4,%5,%6,%7}, {%8,%9}, {%0,%1,%2,%3};"
                 : "+f"(c[0]), "+f"(c[1]), "+f"(c[2]), "+f"(c[3])
                 : "r"(a[0]), "r"(a[1]), "r"(a[2]), "r"(a[3]), "r"(b.x), "r"(b.y));
}
__device__ __forceinline__ uint32_t pack_h2(float lo, float hi) {
    __half l = __float2half_rn(lo);
    __half h = __float2half_rn(hi);
    return (uint32_t)__half_as_ushort(l) | ((uint32_t)__half_as_ushort(h) << 16);
}
// packed f32x2
typedef unsigned long long ull;
__device__ __forceinline__ ull pk2f(float lo, float hi) {
    ull r; asm("mov.b64 %0, {%1, %2};" : "=l"(r) : "f"(lo), "f"(hi)); return r;
}
__device__ __forceinline__ ull fma2(ull a, ull b, ull c) {
    ull d; asm("fma.rn.f32x2 %0, %1, %2, %3;" : "=l"(d) : "l"(a), "l"(b), "l"(c)); return d;
}
__device__ __forceinline__ float2 upk2(ull v) {
    float2 r; asm("mov.b64 {%0, %1}, %2;" : "=f"(r.x), "=f"(r.y) : "l"(v)); return r;
}

// ---------------- parallel precompute (512 threads) --------------------------
__global__ void precompute_kernel(const float* __restrict__ ew0, const float* __restrict__ eb0,
                                  const float* __restrict__ ew1, const float* __restrict__ eb1,
                                  const float* __restrict__ fw0, const float* __restrict__ fb0,
                                  const float* __restrict__ fw1, const float* __restrict__ fb1,
                                  const float* __restrict__ gw0, const float* __restrict__ gb0,
                                  const float* __restrict__ gw1) {
    __shared__ float sh16[2][4][16];
    __shared__ float sh32[4][32];
    __shared__ float shf[4][32];
    __shared__ float shtd[4][31];
    const int t = threadIdx.x;

    if (t < 128) {
        int rev = t >> 6, p = (t >> 4) & 3, i = t & 15;
        float a = (float)(p >> 1), b = (float)(p & 1);
        float x0 = rev ? b : a, x1 = rev ? a : b;
        sh16[rev][p][i] = fmaxf(x0 * ew0[i] + x1 * ew0[16 + i] + eb0[i], 0.f);
    }
    __syncthreads();
    if (t < 128) {
        int p = t >> 5, o = t & 31;
        float s0 = eb1[o], s1 = eb1[o];
        for (int i = 0; i < 16; ++i) {
            s0 += sh16[0][p][i] * ew1[i * 32 + o];
            s1 += sh16[1][p][i] * ew1[i * 32 + o];
        }
        sh32[p][o] = fmaxf(s0, 0.f) + fmaxf(s1, 0.f);
    }
    __syncthreads();
    if (t < 128) {
        int p = t >> 5, o = t & 31;
        float acc = fb0[o];
        for (int i = 0; i < 32; ++i) acc += sh32[p][i] * fw0[i * 32 + o];
        shf[p][o] = fmaxf(acc, 0.f);
    }
    __syncthreads();
    if (t < 124) {
        int p = t / 31, o = t % 31;
        float acc = fb1[o];
        for (int i = 0; i < 32; ++i) acc += shf[p][i] * fw1[i * 31 + o];
        float td = fmaxf(acc, 0.f);
        g_td[p][o] = td;
        shtd[p][o] = td;
    }
    __syncthreads();
    if (t < 256) {
        int p = t >> 6, j = t & 63;
        float acc = gb0[j];
        for (int i = 0; i < 31; ++i) acc += shtd[p][i] * gw0[i * 64 + j];
        g_base[p][j] = acc;
    }
    if (t < 64) g_v[t] = gw0[31 * 64 + t];

    // B fragments: fp16; mma.sync m16n8k16 col-major B layout
    for (int idx = t; idx < 2048; idx += 512) {
        int lane = idx & 31;
        int ks   = (idx >> 5) & 3;
        int nt   = idx >> 7;
        int e    = nt * 8 + (lane >> 2);
        int j0   = ks * 16 + (lane & 3) * 2;
        g_bfrag[idx] = make_uint2(
            pack_h2(gw1[j0 * 128 + e],       gw1[(j0 + 1) * 128 + e]),
            pack_h2(gw1[(j0 + 8) * 128 + e], gw1[(j0 + 9) * 128 + e]));
    }
}

// ---------------- fused main kernel: one CTA per 2 (s,n) pairs ---------------
__global__ __launch_bounds__(128, 4)
void desc_kernel(const float* __restrict__ inputs,
                 const int*   __restrict__ types,
                 const int*   __restrict__ neigh,
                 const float* __restrict__ length,
                 const float* __restrict__ gb1,
                 float*       __restrict__ out)
{
    // single Y panel: 128 rows x 64 fp16 (128B rows), 16B-chunk XOR swizzle
    __shared__ __align__(128) unsigned char ypan[128 * 128];
    __shared__ __align__(16) float4 rts4[128];
    __shared__ __align__(16) float base_s[4 * 68];
    __shared__ __align__(16) float v_s[64];
    __shared__ __align__(16) float td_s[4 * 34];
    __shared__ __align__(16) float4 T_part[2][128];  // [kh][snh*64 + j]
    __shared__ __align__(16) float4 A_s[2][128];

    const int t    = threadIdx.x;
    const int w    = t >> 5;
    const int lane = t & 31;

    // ---- B fragment preload ----
    uint2 bfr[4][4];
#pragma unroll
    for (int ntl = 0; ntl < 4; ++ntl)
#pragma unroll
        for (int ks = 0; ks < 4; ++ks)
            bfr[ntl][ks] = g_bfrag[(((w * 4 + ntl) * 4) + ks) * 32 + lane];

    // ---- stage tables ----
    for (int i = t; i < 256; i += 128) base_s[(i >> 6) * 68 + (i & 63)] = ((const float*)g_base)[i];
    if (t < 64) v_s[t] = g_v[t];
    for (int i = t; i < 124; i += 128) td_s[(i / 31) * 34 + (i % 31)] = ((const float*)g_td)[i];
    if (t < 4) { td_s[t * 34 + 31] = 0.f; td_s[t * 34 + 32] = 0.f; td_s[t * 34 + 33] = 0.f; }

    float b1v[8];
#pragma unroll
    for (int cc = 0; cc < 8; ++cc)
        b1v[cc] = gb1[w * 32 + (cc >> 1) * 8 + (lane & 3) * 2 + (cc & 1)];

    // ---- geometry ----
    const int sn = blockIdx.x * 2 + (t >> 6);
    const int s  = sn >> 11;
    const int n  = sn & (NN - 1);
    float sij; int pp;
    {
        int idx = neigh[(size_t)sn * KK + (t & 63)];
        bool msk = idx < 0;
        int i0 = msk ? 0 : idx;
        float Lx = length[0], Ly = length[1], Lz = length[2];
        const float* pc = inputs + ((size_t)s * NN + n) * 3;
        const float* pn = inputs + ((size_t)s * NN + i0) * 3;
        float dx = pn[0] - pc[0];
        float dy = pn[1] - pc[1];
        float dz = pn[2] - pc[2];
        dx -= Lx * rintf(dx / Lx);
        dy -= Ly * rintf(dy / Ly);
        dz -= Lz * rintf(dz / Lz);
        float rsq = dx * dx + dy * dy + dz * dz;
        float rs  = rsq > 0.f ? rsq : 1.0f;
        float inv = rsqrtf(rs);
        float r   = rs * inv;
        float sw;
        if (r < 6.0f)       sw = inv;
        else if (r < 12.0f) { float u = (r - 6.0f) * (1.0f / 6.0f);
                              sw = inv * (0.5f * __cosf(PI_F * u) + 0.5f); }
        else                sw = 0.f;
        bool valid = (!msk) && (rsq > 0.f);
        sij = valid ? sw : 0.f;
        float f = sij * inv;
        rts4[t] = make_float4(sij, dx * f, dy * f, dz * f);
        int ct = types[(size_t)s * NN + n];
        int nt = types[(size_t)s * NN + i0];
        pp = ct * 2 + nt;
    }
    __syncthreads();

    // ---- phase 2: y row t -> fp16, swizzled 16B-chunk stores ----
    {
        const int rx = t & 7;
        const float2* base2 = (const float2*)(base_s + pp * 68);
        const float2* v2    = (const float2*)v_s;
        const float2* td2   = (const float2*)(td_s + pp * 34);
#pragma unroll
        for (int c = 0; c < 8; ++c) {
            uint32_t wh[4];
#pragma unroll
            for (int q = 0; q < 4; ++q) {
                int jp = c * 4 + q;
                float2 b  = base2[jp];
                float2 vv = v2[jp];
                float2 td = td2[jp & 15];
                float y0 = fmaxf(fmaf(sij, vv.x, b.x), 0.f) + td.x;
                float y1 = fmaxf(fmaf(sij, vv.y, b.y), 0.f) + (((jp & 15) < 15) ? td.y : sij);
                wh[q] = pack_h2(y0, y1);
            }
            int off = t * 128 + (c ^ rx) * 16;
            *(uint4*)(ypan + off) = make_uint4(wh[0], wh[1], wh[2], wh[3]);
        }
    }
    __syncthreads();

    // ---- tail partials: T_part[kh][snh*64+j] = sum_{k in half} y[k,j]*rt[k,:] ----
    {
        const int snh = t >> 6;
        const int kh  = (t >> 5) & 1;
        const int jp  = lane;
        const int chunk = jp >> 2, pos = jp & 3;
        const uint32_t* y32 = (const uint32_t*)ypan;
        const int rbase = snh * 64 + kh * 32;
        ull Tj0a = 0ull, Tj0b = 0ull, Tj1a = 0ull, Tj1b = 0ull;
#pragma unroll
        for (int i = 0; i < 32; ++i) {
            const int row = rbase + i;
            uint32_t o = (uint32_t)(row * 32 + ((chunk ^ (row & 7)) << 2) + pos);
            uint32_t yv = y32[o];
            float2 yf = __half22float2(*(const __half2*)&yv);
            ull y0p = pk2f(yf.x, yf.x);
            ull y1p = pk2f(yf.y, yf.y);
            double2 q = *(const double2*)(rts4 + row);
            ull qxy = __double_as_longlong(q.x), qzw = __double_as_longlong(q.y);
            Tj0a = fma2(y0p, qxy, Tj0a);
            Tj0b = fma2(y0p, qzw, Tj0b);
            Tj1a = fma2(y1p, qxy, Tj1a);
            Tj1b = fma2(y1p, qzw, Tj1b);
        }
        float2 a0 = upk2(Tj0a), b0 = upk2(Tj0b);
        float2 a1 = upk2(Tj1a), b1 = upk2(Tj1b);
        T_part[kh][snh * 64 + 2 * jp]     = make_float4(a0.x, a0.y, b0.x, b0.y);
        T_part[kh][snh * 64 + 2 * jp + 1] = make_float4(a1.x, a1.y, b1.x, b1.y);
    }
    __syncthreads();

    const uint32_t y_b = smem_u32(ypan);

    // ---- MMA + fused epilogue: G = Yh * Wh, 4 mma per (mt,ks) ----
#pragma unroll
    for (int h = 0; h < 2; ++h) {
        ull part01[8], part23[8];
#pragma unroll
        for (int cc = 0; cc < 8; ++cc) { part01[cc] = 0ull; part23[cc] = 0ull; }

#pragma unroll
        for (int mtl = 0; mtl < 4; ++mtl) {
            const int mt = h * 4 + mtl;
            float acc[4][4];
#pragma unroll
            for (int ntl = 0; ntl < 4; ++ntl) {   // bias pre-folded
                acc[ntl][0] = b1v[ntl * 2];
                acc[ntl][1] = b1v[ntl * 2 + 1];
                acc[ntl][2] = b1v[ntl * 2];
                acc[ntl][3] = b1v[ntl * 2 + 1];
            }

            const int arow  = mt * 16 + (lane & 15);
            const int arx   = arow & 7;
            const uint32_t abase = (uint32_t)(arow * 128);
#pragma unroll
            for (int ks = 0; ks < 4; ++ks) {
                uint32_t ah[4];
                uint32_t chsel = (uint32_t)(((ks * 2 + (lane >> 4)) ^ arx) * 16);
                ldm4(ah, y_b + abase + chsel);
#pragma unroll
                for (int ntl = 0; ntl < 4; ++ntl) mma16816(acc[ntl], ah, bfr[ntl][ks]);
            }
            // epilogue: relu + packed A-accumulation
            const int r0 = mt * 16 + (lane >> 2);
            double2 qa = *(const double2*)(rts4 + r0);
            double2 qb = *(const double2*)(rts4 + r0 + 8);
            const ull q0xy = __double_as_longlong(qa.x), q0zw = __double_as_longlong(qa.y);
            const ull q1xy = __double_as_longlong(qb.x), q1zw = __double_as_longlong(qb.y);
#pragma unroll
            for (int cc = 0; cc < 8; ++cc) {
                const int ntl = cc >> 1, c = cc & 1;
                float g0 = fmaxf(acc[ntl][c],     0.f);
                float g1 = fmaxf(acc[ntl][2 + c], 0.f);
                ull g0p = pk2f(g0, g0);
                ull g1p = pk2f(g1, g1);
                part01[cc] = fma2(g0p, q0xy, part01[cc]);
                part23[cc] = fma2(g0p, q0zw, part23[cc]);
                part01[cc] = fma2(g1p, q1xy, part01[cc]);
                part23[cc] = fma2(g1p, q1zw, part23[cc]);
            }
        }

        // unpack + reduce across lane-groups sharing (lane&3): xor 4, 8, 16
#pragma unroll
        for (int cc = 0; cc < 8; ++cc) {
            float2 u01 = upk2(part01[cc]);
            float2 u23 = upk2(part23[cc]);
            float pv[4] = {u01.x, u01.y, u23.x, u23.y};
#pragma unroll
            for (int d = 0; d < 4; ++d) {
                float v = pv[d];
                v += __shfl_xor_sync(0xffffffffu, v, 4);
                v += __shfl_xor_sync(0xffffffffu, v, 8);
                v += __shfl_xor_sync(0xffffffffu, v, 16);
                pv[d] = v;
            }
            if (lane < 4) {
                int e = w * 32 + (cc >> 1) * 8 + lane * 2 + (cc & 1);
                float4 Ta = T_part[0][h * 64 + (e & 63)];
                float4 Tb = T_part[1][h * 64 + (e & 63)];
                A_s[h][e] = make_float4(pv[0] + Ta.x + Tb.x, pv[1] + Ta.y + Tb.y,
                                        pv[2] + Ta.z + Tb.z, pv[3] + Ta.w + Tb.w);
            }
        }
    }
    __syncthreads();

    // ---- D[e,m] = sum_d A[e,d] * A[m,d] per sn-half ----
    const int e = t;
#pragma unroll
    for (int h = 0; h < 2; ++h) {
        float4 a = A_s[h][e];
        size_t gsn = (size_t)blockIdx.x * 2 + h;
        float4* op = (float4*)(out + (gsn * 128 + e) * 16);
#pragma unroll
        for (int m4 = 0; m4 < 4; ++m4) {
            float4 b0 = A_s[h][4 * m4 + 0];
            float4 b1 = A_s[h][4 * m4 + 1];
            float4 b2 = A_s[h][4 * m4 + 2];
            float4 b3 = A_s[h][4 * m4 + 3];
            float4 o;
            o.x = a.x * b0.x + a.y * b0.y + a.z * b0.z + a.w * b0.w;
            o.y = a.x * b1.x + a.y * b1.y + a.z * b1.z + a.w * b1.w;
            o.z = a.x * b2.x + a.y * b2.y + a.z * b2.z + a.w * b2.w;
            o.w = a.x * b3.x + a.y * b3.y + a.z * b3.z + a.w * b3.w;
            op[m4] = o;
        }
    }
}

// ---------------- launch -----------------------------------------------------
extern "C" void kernel_launch(void* const* d_in, const int* in_sizes, int n_in,
                              void* d_out, int out_size) {
    const float* inputs = (const float*)d_in[0];
    const int*   types  = (const int*)d_in[1];
    const int*   neigh  = (const int*)d_in[2];
    const float* length = (const float*)d_in[3];
    const float* ew0 = (const float*)d_in[4];
    const float* eb0 = (const float*)d_in[5];
    const float* ew1 = (const float*)d_in[6];
    const float* eb1 = (const float*)d_in[7];
    const float* fw0 = (const float*)d_in[8];
    const float* fb0 = (const float*)d_in[9];
    const float* fw1 = (const float*)d_in[10];
    const float* fb1 = (const float*)d_in[11];
    const float* gw0 = (const float*)d_in[12];
    const float* gb0 = (const float*)d_in[13];
    const float* gw1 = (const float*)d_in[14];
    const float* gb1 = (const float*)d_in[15];

    precompute_kernel<<<1, 512>>>(ew0, eb0, ew1, eb1, fw0, fb0, fw1, fb1, gw0, gb0, gw1);
    desc_kernel<<<NPAIR, 128>>>(inputs, types, neigh, length, gb1, (float*)d_out);
}